// round 17
// baseline (speedup 1.0000x reference)
#include <cuda_runtime.h>
#include <cuda_fp16.h>
#include <math.h>
#include <stdint.h>

// ---------------------------------------------------------------------------
// Problem constants
// ---------------------------------------------------------------------------
#define T_STEPS 512
#define BATCH   256
#define INF     1024
#define HIDDEN  1024
#define WROW    (INF + HIDDEN)
#define NCLS    512
#define BH      (BATCH * HIDDEN)      // 262144
#define TB      (T_STEPS * BATCH)     // 131072
#define NCTAS   128                   // persistent recurrence grid
#define NGRP    8                     // independent recurrence groups
#define GRP_CTAS 16                   // CTAs per group

// ---------------------------------------------------------------------------
// Device-global scratch (allocation-free rule)
// ---------------------------------------------------------------------------
__device__ __half g_A[(size_t)T_STEPS * BH];      // x-projection + b_ih (fp16)
__device__ __half g_Xh[(size_t)TB * INF];         // X hi (fp16)
__device__ __half g_Hh[(size_t)T_STEPS * BH];     // H hi (fp16)
__device__ __half g_Wih_h[HIDDEN * WROW];         // W_ih hi (row stride WROW)
__device__ __half g_Who_h[NCLS * HIDDEN];         // W_ho hi
__device__ __half g_h0h[BH];                      // h0 hi
// Per-group barrier state, line-padded; gens monotonic across graph replays.
__device__ unsigned g_gcnt[NGRP * 32];
__device__ unsigned g_ggen[NGRP * 32];

// ---------------------------------------------------------------------------
// Portable PTX helpers (sm_80+ features only)
// ---------------------------------------------------------------------------
__device__ __forceinline__ uint32_t smem_to_u32(const void* p) {
    uint32_t a;
    asm("{ .reg .u64 t; cvta.to.shared.u64 t, %1; cvt.u32.u64 %0, t; }"
        : "=r"(a) : "l"(p));
    return a;
}

__device__ __forceinline__ void cp16(uint32_t dst, const void* src) {
    asm volatile("cp.async.cg.shared.global [%0], [%1], 16;"
                 :: "r"(dst), "l"(__cvta_generic_to_global(src)));
}
#define CP_COMMIT()  asm volatile("cp.async.commit_group;" ::: "memory")
#define CP_WAIT(n)   asm volatile("cp.async.wait_group %0;" :: "n"(n) : "memory")

#define LDSM4(r0, r1, r2, r3, addr) \
    asm volatile("ldmatrix.sync.aligned.m8n8.x4.shared.b16 {%0,%1,%2,%3}, [%4];" \
                 : "=r"(r0), "=r"(r1), "=r"(r2), "=r"(r3) : "r"(addr))

// D[16x8] += A[16x16] * B[16x8]^(col)  -- fp16 in, fp32 accum
__device__ __forceinline__ void mma_f16(float* c, const uint32_t* a, const uint32_t* b) {
    asm volatile(
        "mma.sync.aligned.m16n8k16.row.col.f32.f16.f16.f32 "
        "{%0,%1,%2,%3}, {%4,%5,%6,%7}, {%8,%9}, {%0,%1,%2,%3};"
        : "+f"(c[0]), "+f"(c[1]), "+f"(c[2]), "+f"(c[3])
        : "r"(a[0]), "r"(a[1]), "r"(a[2]), "r"(a[3]), "r"(b[0]), "r"(b[1]));
}

// ---------------------------------------------------------------------------
// Fused hi-only fp16 conversion: X + W_ih + W_ho + h0 in ONE launch
// ---------------------------------------------------------------------------
__global__ void convert_all(const float* __restrict__ x,
                            const float* __restrict__ W_ih,
                            const float* __restrict__ W_ho,
                            const float* __restrict__ h0)
{
    const long nx = (long)TB * INF / 4;
    const long n1 = (long)HIDDEN * WROW / 4;
    const long n2 = (long)NCLS * HIDDEN / 4;
    const long n3 = (long)BH / 4;
    const long tot = nx + n1 + n2 + n3;
    for (long i = blockIdx.x * (long)blockDim.x + threadIdx.x; i < tot;
         i += (long)gridDim.x * blockDim.x) {
        const float* s; __half* hi; long e;
        if (i < nx)                { s = x;    hi = g_Xh;    e = i * 4; }
        else if (i < nx + n1)      { s = W_ih; hi = g_Wih_h; e = (i - nx) * 4; }
        else if (i < nx + n1 + n2) { s = W_ho; hi = g_Who_h; e = (i - nx - n1) * 4; }
        else                       { s = h0;   hi = g_h0h;   e = (i - nx - n1 - n2) * 4; }
        float4 v = *(const float4*)(s + e);
        __half2 a, b;
        a.x = __float2half_rn(v.x); a.y = __float2half_rn(v.y);
        b.x = __float2half_rn(v.z); b.y = __float2half_rn(v.w);
        *(__half2*)(hi + e)     = a;
        *(__half2*)(hi + e + 2) = b;
    }
}

// ---------------------------------------------------------------------------
// mma.sync pure-fp16 GEMM (phases 1 & 3), 2 CTAs/SM, templated output type.
// CTA tile 128x128, BK=64, 8 warps (4M x 2N), 2-stage cp.async, 1 sync/chunk.
// ---------------------------------------------------------------------------
#define GROWB  144                   // 128B data + 16 pad
#define G_MAT  (128 * GROWB)         // 18432
#define G_STG  (2 * G_MAT)           // A | B = 36864
#define G_SMEM (2 * G_STG)           // 73728  (x2 CTAs = 147456 < 227KB)

template <typename OT>
__global__ void __launch_bounds__(256, 2)
gemm_f16(const __half* __restrict__ A, long lda,
         const __half* __restrict__ B, long ldb,
         const float* __restrict__ bias, OT* __restrict__ C, long ldc, int K)
{
    extern __shared__ char smem[];
    const uint32_t sb = smem_to_u32(smem);
    const int tid = threadIdx.x, lane = tid & 31, wid = tid >> 5;
    const int wm = wid & 3, wn = wid >> 2;
    const long bm = (long)blockIdx.y * 128;
    const long bn = (long)blockIdx.x * 128;

    float c[2][8][4];
#pragma unroll
    for (int m = 0; m < 2; m++)
#pragma unroll
        for (int n = 0; n < 8; n++)
#pragma unroll
            for (int j = 0; j < 4; j++) c[m][n][j] = 0.0f;

    const uint32_t a_rb  = (uint32_t)(lane & 15) * GROWB + (uint32_t)(lane >> 4) * 16;
    const uint32_t b4_rb = (uint32_t)((lane & 7) + ((lane >> 4) << 3)) * GROWB
                           + (uint32_t)((lane >> 3) & 1) * 16;

    auto load_chunk = [&](int kc, int stage) {
        uint32_t base = sb + stage * G_STG;
#pragma unroll
        for (int it = 0; it < 4; it++) {
            int u = tid + it * 256;
            int row = u >> 3, seg = u & 7;
            uint32_t so = row * GROWB + seg * 16;
            cp16(base + so,         A + (bm + row) * lda + kc + seg * 8);
            cp16(base + G_MAT + so, B + (bn + row) * ldb + kc + seg * 8);
        }
    };

    const int nchunk = K >> 6;      // BK = 64
    load_chunk(0, 0);
    CP_COMMIT();

    for (int ch = 0; ch < nchunk; ch++) {
        CP_WAIT(0);
        __syncthreads();          // chunk ch landed + visible to all threads
        if (ch + 1 < nchunk) {
            load_chunk((ch + 1) << 6, (ch + 1) & 1);
            CP_COMMIT();
        }

        const uint32_t base = sb + (ch & 1) * G_STG;
#pragma unroll
        for (int k16 = 0; k16 < 4; k16++) {
            const uint32_t kb = k16 * 32;
            uint32_t ah[2][4], bh[8][2];
#pragma unroll
            for (int m = 0; m < 2; m++) {
                uint32_t ra = base + (uint32_t)(wm * 32 + m * 16) * GROWB + kb + a_rb;
                LDSM4(ah[m][0], ah[m][1], ah[m][2], ah[m][3], ra);
            }
#pragma unroll
            for (int p = 0; p < 4; p++) {
                uint32_t rb = base + G_MAT + (uint32_t)(wn * 64 + p * 16) * GROWB + kb + b4_rb;
                LDSM4(bh[2*p][0], bh[2*p][1], bh[2*p+1][0], bh[2*p+1][1], rb);
            }
#pragma unroll
            for (int m = 0; m < 2; m++)
#pragma unroll
                for (int n = 0; n < 8; n++)
                    mma_f16(c[m][n], ah[m], bh[n]);
        }
    }

#pragma unroll
    for (int m = 0; m < 2; m++) {
        long r0 = bm + wm * 32 + m * 16 + (lane >> 2);
        long r1 = r0 + 8;
#pragma unroll
        for (int n = 0; n < 8; n++) {
            long col = bn + wn * 64 + n * 8 + (lane & 3) * 2;
            float bx = bias[col], by = bias[col + 1];
            float o00 = c[m][n][0] + bx, o01 = c[m][n][1] + by;
            float o10 = c[m][n][2] + bx, o11 = c[m][n][3] + by;
            if constexpr (sizeof(OT) == 4) {
                float2 v0 = { o00, o01 }, v1 = { o10, o11 };
                *(float2*)((float*)C + r0 * ldc + col) = v0;
                *(float2*)((float*)C + r1 * ldc + col) = v1;
            } else {
                __half2 v0, v1;
                v0.x = __float2half_rn(o00); v0.y = __float2half_rn(o01);
                v1.x = __float2half_rn(o10); v1.y = __float2half_rn(o11);
                *(__half2*)((__half*)C + r0 * ldc + col) = v0;
                *(__half2*)((__half*)C + r1 * ldc + col) = v1;
            }
        }
    }
}

// ---------------------------------------------------------------------------
// Per-group barrier (16 CTAs); groups fully decoupled closed systems.
// ---------------------------------------------------------------------------
__device__ __forceinline__ void group_bar(int g, unsigned& lgen)
{
    __syncthreads();
    if (threadIdx.x == 0) {
        __threadfence();
        if (atomicAdd(&g_gcnt[g * 32], 1u) == GRP_CTAS - 1) {
            atomicExch(&g_gcnt[g * 32], 0u);
            __threadfence();
            atomicAdd(&g_ggen[g * 32], 1u);
        } else {
            while (*(volatile unsigned*)&g_ggen[g * 32] == lgen) { __nanosleep(16); }
            __threadfence();
        }
        lgen++;
    }
    __syncthreads();
}

// ---------------------------------------------------------------------------
// Persistent recurrence (fp16 x1, W resident, BK=256, 3-stage ring, rotation):
//   h_t = tanh(g_A[t] + h_{t-1} @ W_h^T)
// 128 CTAs = 8 groups x 16; CTA tile 32(batch) x 64(hidden); warps 2M x 4N.
// 4 chunks/step -> 4 syncthreads/step.  Proven ordering preserved:
// CP_WAIT -> __syncthreads -> load -> compute (the R15 race is impossible).
// h_last (t = T-1) written directly to the output buffer.
// ---------------------------------------------------------------------------
#define A_RB      528                        // 512B data + 16 pad (streamed A)
#define RB_ROWB   2064                       // 2048B data + 16 pad (resident W)
#define RBH_SZ    (64 * RB_ROWB)             // 132096
#define RA_SZ     (32 * A_RB)                // 16896 per stage
#define R_STAGES  3
#define R2_SMEM   (RBH_SZ + R_STAGES * RA_SZ)  // 182784

__global__ void __launch_bounds__(256, 1)
rnn_recur(float* __restrict__ hlast_out)
{
    extern __shared__ char smem[];
    const uint32_t sb = smem_to_u32(smem);
    const int tid = threadIdx.x, lane = tid & 31, wid = tid >> 5;
    const int wm = wid & 1, wn = wid >> 1;       // 2 x 4 warp grid
    const int grp = blockIdx.x >> 4;             // group (0..7)
    const int gn  = blockIdx.x & 15;             // n tile within group
    const int bm  = grp * 32;                    // batch rows [bm, bm+32)
    const int bn  = gn * 64;                     // hidden cols [bn, bn+64)
    const int start = gn >> 2;                   // rotation: own-column chunk first

    const uint32_t a_rb   = (uint32_t)(lane & 15) * A_RB + (uint32_t)(lane >> 4) * 16;
    const uint32_t b4h_rb = (uint32_t)((lane & 7) + ((lane >> 4) << 3)) * RB_ROWB
                            + (uint32_t)((lane >> 3) & 1) * 16;

    // ---- Resident W_h hi tile: 64 rows x 1024 fp16 (8192 x 16B units)
    for (int u = tid; u < 8192; u += 256) {
        int row = u >> 7, seg = u & 127;
        cp16(sb + row * RB_ROWB + seg * 16,
             g_Wih_h + (size_t)(bn + row) * WROW + INF + seg * 8);
    }
    CP_COMMIT();

    unsigned lgen = *(volatile unsigned*)&g_ggen[grp * 32];

    // Epilogue coordinates + first-step pre-activation prefetch (fp16)
    const int er0 = bm + wm * 16 + (lane >> 2);
    const int ec0 = bn + wn * 16 + (lane & 3) * 2;
    __half2 pre[2][2];
#pragma unroll
    for (int n = 0; n < 2; n++) {
        pre[n][0] = *(const __half2*)(g_A + (size_t)er0       * HIDDEN + ec0 + n * 8);
        pre[n][1] = *(const __half2*)(g_A + (size_t)(er0 + 8) * HIDDEN + ec0 + n * 8);
    }

    for (int t = 0; t < T_STEPS; t++) {
        const __half* hh = (t == 0) ? g_h0h : (g_Hh + (size_t)(t - 1) * BH);
        const size_t ob = (size_t)t * BH;

        float c[2][4];
#pragma unroll
        for (int n = 0; n < 2; n++)
#pragma unroll
            for (int j = 0; j < 4; j++) c[n][j] = 0.0f;

        // Stream A hi chunk cc (BK=256): 32 rows x 32 segs = 1024 units (4/thread)
        auto load_chunk = [&](int cc, int stage) {
            uint32_t base = sb + RBH_SZ + stage * RA_SZ;
            const int kc = cc << 8;
#pragma unroll
            for (int it = 0; it < 4; it++) {
                int u = tid + it * 256;
                int row = u >> 5, seg = u & 31;
                cp16(base + row * A_RB + seg * 16,
                     hh + (size_t)(bm + row) * HIDDEN + kc + seg * 8);
            }
        };

        // Prologue: chunks start, start+1 into stages 0, 1
        load_chunk(start & 3, 0);
        CP_COMMIT();
        load_chunk((start + 1) & 3, 1);
        CP_COMMIT();

#pragma unroll
        for (int i = 0; i < 4; i++) {
            const int cc = (start + i) & 3;
            // Wait for chunk i (groups complete FIFO), then make visible.
            if (i < 3) CP_WAIT(1);
            else       CP_WAIT(0);
            __syncthreads();       // landing visible to ALL threads; stage reuse safe
            if (i < 2) {
                load_chunk((start + i + 2) & 3, (i + 2) % 3);
                CP_COMMIT();
            }

            const uint32_t abase = sb + RBH_SZ + (i % 3) * RA_SZ
                                   + (uint32_t)(wm * 16) * A_RB + a_rb;
            const uint32_t bhb   = sb + (uint32_t)(wn * 16) * RB_ROWB
                                   + (uint32_t)(cc << 9) + b4h_rb;

            // Fragment-pipelined k16 loop (16 iters, double-buffered)
            uint32_t ah[2][4], bh[2][2][2];

#define R_LD(k16, buf) do { \
        LDSM4(ah[buf][0], ah[buf][1], ah[buf][2], ah[buf][3], \
              abase + (uint32_t)((k16) * 32)); \
        LDSM4(bh[buf][0][0], bh[buf][0][1], bh[buf][1][0], bh[buf][1][1], \
              bhb + (uint32_t)((k16) * 32)); \
    } while (0)

            R_LD(0, 0);
#pragma unroll
            for (int k16 = 0; k16 < 16; k16++) {
                if (k16 < 15) R_LD(k16 + 1, (k16 + 1) & 1);
                const int b = k16 & 1;
#pragma unroll
                for (int n = 0; n < 2; n++)
                    mma_f16(c[n], ah[b], bh[b][n]);
            }
#undef R_LD
        }

        // Epilogue: tanh(acc + pre), store fp16 hi (+ fp32 h_last at t=T-1)
        {
            const int r0 = er0, r1 = er0 + 8;
#pragma unroll
            for (int n = 0; n < 2; n++) {
                const int col = ec0 + n * 8;
                float2 p0 = __half22float2(pre[n][0]);
                float2 p1 = __half22float2(pre[n][1]);
                float h00 = tanhf(c[n][0] + p0.x);
                float h01 = tanhf(c[n][1] + p0.y);
                float h10 = tanhf(c[n][2] + p1.x);
                float h11 = tanhf(c[n][3] + p1.y);

                __half2 th;
                th.x = __float2half_rn(h00); th.y = __float2half_rn(h01);
                *(__half2*)(g_Hh + ob + (size_t)r0 * HIDDEN + col) = th;
                th.x = __float2half_rn(h10); th.y = __float2half_rn(h11);
                *(__half2*)(g_Hh + ob + (size_t)r1 * HIDDEN + col) = th;

                if (t == T_STEPS - 1) {
                    float2 f0 = { h00, h01 }, f1 = { h10, h11 };
                    *(float2*)(hlast_out + (size_t)r0 * HIDDEN + col) = f0;
                    *(float2*)(hlast_out + (size_t)r1 * HIDDEN + col) = f1;
                }
            }
        }

        // Prefetch next step's pre-activations BEFORE the barrier
        if (t + 1 < T_STEPS) {
            const size_t ob1 = (size_t)(t + 1) * BH;
#pragma unroll
            for (int n = 0; n < 2; n++) {
                pre[n][0] = *(const __half2*)(g_A + ob1 + (size_t)er0       * HIDDEN + ec0 + n * 8);
                pre[n][1] = *(const __half2*)(g_A + ob1 + (size_t)(er0 + 8) * HIDDEN + ec0 + n * 8);
            }
        }

        group_bar(grp, lgen);   // 16-CTA rendezvous; groups fully decoupled
    }
}

// ---------------------------------------------------------------------------
// In-place softmax over rows of 512 floats
// ---------------------------------------------------------------------------
__global__ void softmax512(float* __restrict__ O)
{
    __shared__ float red[4];
    long row = blockIdx.x;
    float4* p = (float4*)(O + row * (long)NCLS);
    float4 v = p[threadIdx.x];

    float m = fmaxf(fmaxf(v.x, v.y), fmaxf(v.z, v.w));
#pragma unroll
    for (int o = 16; o > 0; o >>= 1)
        m = fmaxf(m, __shfl_xor_sync(0xffffffffu, m, o));
    int warp = threadIdx.x >> 5;
    if ((threadIdx.x & 31) == 0) red[warp] = m;
    __syncthreads();
    m = fmaxf(fmaxf(red[0], red[1]), fmaxf(red[2], red[3]));

    float4 e;
    e.x = __expf(v.x - m);
    e.y = __expf(v.y - m);
    e.z = __expf(v.z - m);
    e.w = __expf(v.w - m);
    float s = e.x + e.y + e.z + e.w;
#pragma unroll
    for (int o = 16; o > 0; o >>= 1)
        s += __shfl_xor_sync(0xffffffffu, s, o);
    __syncthreads();
    if ((threadIdx.x & 31) == 0) red[warp] = s;
    __syncthreads();
    s = red[0] + red[1] + red[2] + red[3];

    float inv = 1.0f / s;
    e.x *= inv; e.y *= inv; e.z *= inv; e.w *= inv;
    p[threadIdx.x] = e;
}

// ---------------------------------------------------------------------------
// Launch (5 graph nodes)
// ---------------------------------------------------------------------------
extern "C" void kernel_launch(void* const* d_in, const int* in_sizes, int n_in,
                              void* d_out, int out_size)
{
    const float* x    = (const float*)d_in[0];
    const float* h0   = (const float*)d_in[1];
    const float* W_ih = (const float*)d_in[2];
    const float* b_ih = (const float*)d_in[3];
    const float* W_ho = (const float*)d_in[4];
    const float* b_ho = (const float*)d_in[5];
    float*       out  = (float*)d_out;

    __half *pA, *pXh, *pHh, *pWih_h, *pWoh;
    cudaGetSymbolAddress((void**)&pA,     g_A);
    cudaGetSymbolAddress((void**)&pXh,    g_Xh);
    cudaGetSymbolAddress((void**)&pHh,    g_Hh);
    cudaGetSymbolAddress((void**)&pWih_h, g_Wih_h);
    cudaGetSymbolAddress((void**)&pWoh,   g_Who_h);

    cudaFuncSetAttribute(gemm_f16<__half>,
                         cudaFuncAttributeMaxDynamicSharedMemorySize, G_SMEM);
    cudaFuncSetAttribute(gemm_f16<float>,
                         cudaFuncAttributeMaxDynamicSharedMemorySize, G_SMEM);
    cudaFuncSetAttribute(rnn_recur,
                         cudaFuncAttributeMaxDynamicSharedMemorySize, R2_SMEM);

    // #1: all fp16 conversions in one launch
    convert_all<<<4096, 256>>>(x, W_ih, W_ho, h0);

    // #2: Phase 1 -- g_A = Xh @ Wx_h^T + b_ih   (pure fp16, fp16 output)
    {
        dim3 grid(HIDDEN / 128, TB / 128);   // (8, 1024)
        gemm_f16<__half><<<grid, 256, G_SMEM>>>(pXh, INF, pWih_h, WROW,
                                                b_ih, pA, HIDDEN, INF);
    }

    // #3: Phase 2 -- persistent recurrence; writes h_last directly to out
    rnn_recur<<<NCTAS, 256, R2_SMEM>>>(out + (long)TB * NCLS);

    // #4/#5: Phase 3 -- out = Hh @ Who_h^T + b_ho (fp32 output), softmax
    {
        dim3 grid(NCLS / 128, TB / 128);     // (4, 1024)
        gemm_f16<float><<<grid, 256, G_SMEM>>>(pHh, HIDDEN, pWoh, HIDDEN,
                                               b_ho, out, NCLS, HIDDEN);
        softmax512<<<TB, 128>>>(out);
    }
}